// round 12
// baseline (speedup 1.0000x reference)
#include <cuda_runtime.h>
#include <math.h>
#include <stdint.h>

#define BATCH    2048
#define NCLS     100
#define FH       64        // FEATURE_NUMS/2
#define O        9         // POLICY_NUMS + 2
#define NBIN     16
#define NBLOCKS  512       // each block: 4 logits rows (1/warp) + 2 policy pairs
#define PPB      2         // pairs per block (warp per pair, warps 0-1)

// ---------------- scratch (device globals; zero at load, re-zeroed each run) ---
__device__ float g_ce, g_kl;
// per-k stats [k][q], q: 0 Su,1 Su2,2 Sv,3 Sv2,4 Sb,5 Sa,6 Sb2,7 Sa2
__device__ float g_acc[O * 8];
__device__ float g_SA[8 * NBIN], g_SB[8 * NBIN];
__device__ int   g_c1[8 * NBIN], g_c2[8 * NBIN];
__device__ unsigned int g_cnt;

__global__ __launch_bounds__(128) void fused_kernel(
    const float* __restrict__ sl, const float* __restrict__ tl,
    const float* __restrict__ sp, const float* __restrict__ tp,
    const float* __restrict__ W1, const float* __restrict__ b1,
    const float* __restrict__ W2, const float* __restrict__ b2,
    const int*  __restrict__ tg, float* __restrict__ out)
{
    __shared__ float  sPair[PPB * 36];     // per-pair as[9],bs[9],at[9],bt[9]
    __shared__ int    sTT[PPB * 16];       // targets for this block's 4 rows
    __shared__ float  s_ce, s_kl;
    __shared__ float  m_sh[128], p_sh[128];
    __shared__ float  matchS[8], pairS[8], D2s[O], E3s[7], E12[2], facc[O * 8];
    __shared__ int s_last;

    const int tid  = threadIdx.x;
    const int bid  = blockIdx.x;
    const int wid  = tid >> 5;
    const int lane = tid & 31;

    // ---------- phase 0: stage targets + init; prefetch policy operands ----------
    if (tid == 0) { s_ce = 0.f; s_kl = 0.f; }
    if (tid < 8)
        ((int4*)sTT)[tid] = ((const int4*)(tg + bid * 32))[tid];

    // policy: warps 0-1 = pairs; lane -> role (4) x feature-eighth (8)
    const int j    = bid * PPB + wid;      // global pair (valid for wid<2)
    const int role = lane >> 3;            // 0:as 1:bs 2:at 3:bt
    const int q8   = lane & 7;
    const int c0   = q8 * 8;
    float4 fv0, fv1;
    float4 wv0[O], wv1[O];                 // weights straight to registers
    if (wid < PPB) {
        const float* fbase = ((role < 2) ? sp : tp) + (2 * j + (role & 1)) * FH + c0;
        fv0 = ((const float4*)fbase)[0];
        fv1 = ((const float4*)fbase)[1];
        const float* wbase = ((role >= 2) ? W1 : W2) + (role & 1) * FH + c0;
#pragma unroll
        for (int k = 0; k < O; k++) {
            const float4* w = (const float4*)(wbase + k * 2 * FH);
            wv0[k] = w[0];
            wv1[k] = w[1];
        }
    }

    // ---------- logits: CE + KL, one row per warp (no max-sub) ----------
    // exp(x) = (exp(x/4))^4 -> one MUFU per student element; U,V folded into D.
    int row = bid * 4 + wid;
    const float4* s4 = (const float4*)(sl + row * NCLS);
    const float4* t4 = (const float4*)(tl + row * NCLS);

    float sv[4], tv[4];
    bool act = lane < 25;                   // 25 float4 = 100 cols
    float S1 = 0.f, S4 = 0.f, T4 = 0.f, D = 0.f;
    if (act) {
        float4 a = s4[lane], b = t4[lane];
        sv[0]=a.x; sv[1]=a.y; sv[2]=a.z; sv[3]=a.w;
        tv[0]=b.x; tv[1]=b.y; tv[2]=b.z; tv[3]=b.w;
#pragma unroll
        for (int i = 0; i < 4; i++) {
            float s4a = sv[i] * 0.25f;
            float ta  = tv[i] * 0.25f;
            float es  = __expf(s4a);
            float te  = __expf(ta);
            float es2 = es * es;
            S1 += es2 * es2;                // exp(sv)
            S4 += es;
            T4 += te;
            D  += te * (ta - s4a);          // U - V folded
        }
    }
#pragma unroll
    for (int o = 16; o; o >>= 1) {
        S1 += __shfl_down_sync(0xffffffffu, S1, o);
        S4 += __shfl_down_sync(0xffffffffu, S4, o);
        T4 += __shfl_down_sync(0xffffffffu, T4, o);
        D  += __shfl_down_sync(0xffffffffu, D,  o);
    }

    // CE label (in [0,10) -> data lives in lanes 0..2 of the float4 layout)
    int label = tg[row * 8];
    int elem = label & 3;
    float cand = (elem == 0) ? sv[0] : (elem == 1) ? sv[1] : (elem == 2) ? sv[2] : sv[3];
    float slab = __shfl_sync(0xffffffffu, cand, label >> 2);

    float ce_w = 0.f, kl_w = 0.f;
    if (lane == 0) {
        kl_w = D / T4 + __logf(S4) - __logf(T4);
        ce_w = __logf(S1) - slab;
    }

    __syncthreads();   // sTT staged, s_ce/s_kl init visible

    if (lane == 0) { atomicAdd(&s_ce, ce_w); atomicAdd(&s_kl, kl_w); }

    // ---------- policy GEMV (warps 0-1): 9 dots of 8 features, all registers ----
    if (wid < PPB) {
        float acc[O];
#pragma unroll
        for (int k = 0; k < O; k++) {
            acc[k] = fv0.x * wv0[k].x + fv0.y * wv0[k].y
                   + fv0.z * wv0[k].z + fv0.w * wv0[k].w
                   + fv1.x * wv1[k].x + fv1.y * wv1[k].y
                   + fv1.z * wv1[k].z + fv1.w * wv1[k].w;
        }
        // reduce feature-eighths within each role group of 8 lanes
#pragma unroll
        for (int k = 0; k < O; k++) {
            acc[k] += __shfl_down_sync(0xffffffffu, acc[k], 4);
            acc[k] += __shfl_down_sync(0xffffffffu, acc[k], 2);
            acc[k] += __shfl_down_sync(0xffffffffu, acc[k], 1);
        }
        if (q8 == 0) {
            float* dst = sPair + wid * 36 + role * 9;
#pragma unroll
            for (int k = 0; k < O; k++) dst[k] = acc[k];
        }
    }
    __syncthreads();

    // ---------- merges (atomic-free in-block; one RED per stat) ----------
    // histogram: all 128 threads, entry (tc, v)
    {
        int tc = tid >> 4, v = tid & 15;
        float fSA = 0.f, fSB = 0.f;
        int c1 = 0, c2 = 0;
#pragma unroll
        for (int p = 0; p < PPB; p++) {
            int tv1 = sTT[p * 16 + tc];
            int tv2 = sTT[p * 16 + 8 + tc];
            float av = sPair[p * 36 + 1 + tc];
            float bv = sPair[p * 36 + 10 + tc];
            if (tv1 == v) { fSA += av; c1++; }
            if (tv2 == v) { fSB += bv; c2++; }
        }
        atomicAdd(&g_SA[tid], fSA);
        atomicAdd(&g_SB[tid], fSB);
        atomicAdd(&g_c1[tid], c1);
        atomicAdd(&g_c2[tid], c2);
    }
    // stats: threads 0..71
    if (tid < O * 8) {
        int k = tid >> 3, q = tid & 7;
        // q0,1: u=bs-bt (q1 squared); q2,3: v=as-at; q4:bs q5:as q6:bs^2 q7:as^2
        int off1 = (q < 2) ? 9 : (q < 4) ? 0 : ((q == 4 || q == 6) ? 9 : 0);
        bool use_sub = (q < 4);
        bool sq = (q < 4) ? (q & 1) : (q >= 6);
        float s = 0.f;
#pragma unroll
        for (int p = 0; p < PPB; p++) {
            const float* r = sPair + p * 36;
            float x = r[off1 + k];
            if (use_sub) x -= r[off1 + 18 + k];
            s += sq ? x * x : x;
        }
        atomicAdd(&g_acc[tid], s);
    } else if (tid == 126) {
        atomicAdd(&g_ce, s_ce);
    } else if (tid == 127) {
        atomicAdd(&g_kl, s_kl);
    }

    // ================= last-block epilogue (all fp32) =================
    __threadfence();
    if (tid == 0)
        s_last = (atomicAdd(&g_cnt, 1u) == (unsigned)(NBLOCKS - 1));
    __syncthreads();
    if (!s_last) return;
    __threadfence();

    volatile float* vacc = g_acc;
    volatile float* vSA  = g_SA;
    volatile float* vSB  = g_SB;
    volatile int*   vc1  = g_c1;
    volatile int*   vc2  = g_c2;

    const float n = 1024.f;
    const float N2 = 1048576.f;
    const float INV_N2 = 1.f / 1048576.f;

    // phase A: per-bin pair sums (all 128 thr) + acc copy (72 thr)
    {
        int tc = tid >> 4;
        float c1 = (float)vc1[tid];
        float c2 = (float)vc2[tid];
        float bias = b2[tc + 1];
        m_sh[tid] = c1 * vSB[tid] + c2 * vSA[tid] + c1 * c2 * bias;
        p_sh[tid] = c1 * c2;
    }
    if (tid < O * 8) facc[tid] = vacc[tid];
    __syncthreads();

    // phase B: per-tc bin sums (8 thr) + per-k D2 (9 thr, disjoint range)
    if (tid < 8) {
        float ms = 0.f, ps = 0.f;
#pragma unroll
        for (int v = 0; v < NBIN; v++) { ms += m_sh[tid * NBIN + v]; ps += p_sh[tid * NBIN + v]; }
        matchS[tid] = ms; pairS[tid] = ps;
    } else if (tid >= 32 && tid < 32 + O) {
        int k = tid - 32;
        float Su = facc[k*8+0], Su2 = facc[k*8+1], Sv = facc[k*8+2], Sv2 = facc[k*8+3];
        float ck = b2[k] - b1[k];
        D2s[k] = n * Su2 + n * Sv2 + 2.f * Su * Sv
               + 2.f * ck * n * (Su + Sv) + N2 * ck * ck;
    }
    __syncthreads();

    // phase C: E3 per policy column (7 thr), E1, E2
    if (tid < 7) {
        int k = tid + 2, t = tid + 1;
        float Sb = facc[k*8+4], Sa = facc[k*8+5], Sb2 = facc[k*8+6], Sa2 = facc[k*8+7];
        float ck = b2[k];
        float Sp2 = n * Sb2 + n * Sa2 + 2.f * Sb * Sa
                  + 2.f * ck * n * (Sb + Sa) + N2 * ck * ck;
        float Sp  = n * (Sb + Sa) + N2 * ck;
        float Spg = 2.f * matchS[t] - Sp;
        E3s[tid] = Sp2 - 2.f * Spg + N2;
    } else if (tid == 8) {
        // gId == 1 +/- few float ULP  =>  log(gId) == gId - 1
        float gId = (1.0f / 1023.0f + 1.0f) - 1.0f / 1023.0f;
        float Sb0 = facc[0*8+4], Sa0 = facc[0*8+5];
        E12[0] = (n * gId * (gId - 1.0f) - gId * (Sb0 + Sa0 + n * b2[0])) * INV_N2;
    } else if (tid == 9) {
        float gCp = (1.0f / 99.0f + 1.0f) - 1.0f / 99.0f;
        E12[1] = 0.5f * (pairS[0] * gCp * (gCp - 1.0f) - gCp * matchS[0]) * INV_N2;
    }
    __syncthreads();

    // phase D: scalar combine
    if (tid == 0) {
        float sumDP = 0.f;
#pragma unroll
        for (int k = 2; k < O; k++) sumDP += D2s[k];
        float klp = D2s[0] * INV_N2 + 0.5f * D2s[1] * INV_N2
                  + sumDP * (0.001f * INV_N2 / 7.0f);

        float E3 = 0.f;
#pragma unroll
        for (int m = 0; m < 7; m++) E3 += E3s[m];
        E3 *= 0.001f * INV_N2 / 7.0f;

        float ce = *(volatile float*)&g_ce;
        float kl = *(volatile float*)&g_kl;
        float policy = klp + E12[0] + E12[1] + E3;
        out[0] = ce * (1.0f / (float)BATCH)
               + kl * (16.0f / ((float)BATCH * (float)NCLS))
               + policy;
    }
    __syncthreads();

    // reset scratch for next replay
    if (tid < O * 8) g_acc[tid] = 0.f;
    g_SA[tid] = 0.f; g_SB[tid] = 0.f; g_c1[tid] = 0; g_c2[tid] = 0;
    if (tid == 0) { g_ce = 0.f; g_kl = 0.f; g_cnt = 0u; }
}

// ---------------- launch ----------------
extern "C" void kernel_launch(void* const* d_in, const int* in_sizes, int n_in,
                              void* d_out, int out_size)
{
    const float* sl = (const float*)d_in[0];   // student_logits (2048,100)
    const float* tl = (const float*)d_in[1];   // teacher_logits (2048,100)
    const float* sp = (const float*)d_in[2];   // student_policy (2048,64)
    const float* tp = (const float*)d_in[3];   // teacher_policy (2048,64)
    const float* W1 = (const float*)d_in[4];   // (9,128)
    const float* b1 = (const float*)d_in[5];   // (9,)
    const float* W2 = (const float*)d_in[6];   // (9,128)
    const float* b2 = (const float*)d_in[7];   // (9,)
    const int*   tg = (const int*)d_in[8];     // (2048,1,8)

    fused_kernel<<<NBLOCKS, 128>>>(sl, tl, sp, tp, W1, b1, W2, b2, tg, (float*)d_out);
}

// round 13
// speedup vs baseline: 1.1544x; 1.1544x over previous
#include <cuda_runtime.h>
#include <math.h>
#include <stdint.h>

#define BATCH    2048
#define NCLS     100
#define FH       64        // FEATURE_NUMS/2
#define O        9         // POLICY_NUMS + 2
#define NBIN     16
#define NBLOCKS  256       // each block: 8 logits rows (1/warp) + 4 policy pairs
#define WSZ      (O * 2 * FH)    // 1152 floats per weight matrix
#define PPB      4         // pairs per block (warp per pair, warps 0-3)

// ---------------- scratch (device globals; zero at load, re-zeroed each run) ---
__device__ float g_ce, g_kl;
// per-k stats [k][q], q: 0 Su,1 Su2,2 Sv,3 Sv2,4 Sb,5 Sa,6 Sb2,7 Sa2
__device__ float g_acc[O * 8];
__device__ float g_SA[8 * NBIN], g_SB[8 * NBIN];
__device__ int   g_c1[8 * NBIN], g_c2[8 * NBIN];
__device__ unsigned int g_cnt;

__global__ __launch_bounds__(256) void fused_kernel(
    const float* __restrict__ sl, const float* __restrict__ tl,
    const float* __restrict__ sp, const float* __restrict__ tp,
    const float* __restrict__ W1, const float* __restrict__ b1,
    const float* __restrict__ W2, const float* __restrict__ b2,
    const int*  __restrict__ tg, float* __restrict__ out)
{
    __shared__ float  Ws[2 * WSZ];         // [W2 | W1]
    __shared__ float  sPair[PPB * 36];     // per-pair as[9],bs[9],at[9],bt[9]
    __shared__ int    sTT[PPB * 16];       // targets for this block's 8 rows
    __shared__ float  s_ce, s_kl;
    __shared__ float  m_sh[128], p_sh[128];
    __shared__ float  matchS[8], pairS[8], D2s[O], E3s[7], E12[2], facc[O * 8];
    __shared__ int s_last;

    const int tid  = threadIdx.x;
    const int bid  = blockIdx.x;
    const int wid  = tid >> 5;
    const int lane = tid & 31;

    // ---------- phase 0: stage weights/targets, prefetch features ----------
    if (tid == 0) { s_ce = 0.f; s_kl = 0.f; }
    {
        const float4* w2v = (const float4*)W2;   // 288 float4
        const float4* w1v = (const float4*)W1;
        float4* wsv = (float4*)Ws;
#pragma unroll
        for (int i = tid; i < 576; i += 256)
            wsv[i] = (i < 288) ? w2v[i] : w1v[i - 288];
        if (tid < 16)
            ((int4*)sTT)[tid] = ((const int4*)(tg + bid * 64))[tid];
    }

    // policy indices: warps 0-3 = pairs; lane -> role (4) x feature-eighth (8)
    const int j    = bid * PPB + wid;      // global pair (valid for wid<4)
    const int role = lane >> 3;            // 0:as 1:bs 2:at 3:bt
    const int q8   = lane & 7;
    const int c0   = q8 * 8;
    float4 fv0, fv1;
    if (wid < PPB) {
        const float* fbase = ((role < 2) ? sp : tp) + (2 * j + (role & 1)) * FH + c0;
        fv0 = ((const float4*)fbase)[0];
        fv1 = ((const float4*)fbase)[1];
    }

    // ---------- logits: CE + KL, ONE row per warp (no max-sub) ----------
    // exp(x) = (exp(x/4))^4 -> one MUFU per student element; U,V folded into D.
    int row = bid * 8 + wid;
    const float4* s4 = (const float4*)(sl + row * NCLS);
    const float4* t4 = (const float4*)(tl + row * NCLS);

    float sv[4], tv[4];
    bool act = lane < 25;                   // 25 float4 = 100 cols
    float S1 = 0.f, S4 = 0.f, T4 = 0.f, D = 0.f;
    if (act) {
        float4 a = s4[lane], b = t4[lane];
        sv[0]=a.x; sv[1]=a.y; sv[2]=a.z; sv[3]=a.w;
        tv[0]=b.x; tv[1]=b.y; tv[2]=b.z; tv[3]=b.w;
#pragma unroll
        for (int i = 0; i < 4; i++) {
            float s4a = sv[i] * 0.25f;
            float ta  = tv[i] * 0.25f;
            float es  = __expf(s4a);
            float te  = __expf(ta);
            float es2 = es * es;
            S1 += es2 * es2;                // exp(sv)
            S4 += es;
            T4 += te;
            D  += te * (ta - s4a);          // U - V folded
        }
    }
#pragma unroll
    for (int o = 16; o; o >>= 1) {
        S1 += __shfl_down_sync(0xffffffffu, S1, o);
        S4 += __shfl_down_sync(0xffffffffu, S4, o);
        T4 += __shfl_down_sync(0xffffffffu, T4, o);
        D  += __shfl_down_sync(0xffffffffu, D,  o);
    }

    // CE label (in [0,10) -> data lives in lanes 0..2 of the float4 layout)
    int label = tg[row * 8];
    int elem = label & 3;
    float cand = (elem == 0) ? sv[0] : (elem == 1) ? sv[1] : (elem == 2) ? sv[2] : sv[3];
    float slab = __shfl_sync(0xffffffffu, cand, label >> 2);

    float ce_w = 0.f, kl_w = 0.f;
    if (lane == 0) {
        kl_w = D / T4 + __logf(S4) - __logf(T4);
        ce_w = __logf(S1) - slab;
    }

    __syncthreads();   // Ws, sTT, s_ce init visible

    if (lane == 0) { atomicAdd(&s_ce, ce_w); atomicAdd(&s_kl, kl_w); }

    // ---------- policy GEMV (warps 0-3): 9 dots of 8 features per thread ----------
    if (wid < PPB) {
        const float* wbase = Ws + ((role >= 2) ? WSZ : 0) + (role & 1) * FH + c0;
        float acc[O];
#pragma unroll
        for (int k = 0; k < O; k++) {
            const float4* w = (const float4*)(wbase + k * 2 * FH);
            float4 w0 = w[0], w1v = w[1];
            acc[k] = fv0.x * w0.x + fv0.y * w0.y + fv0.z * w0.z + fv0.w * w0.w
                   + fv1.x * w1v.x + fv1.y * w1v.y + fv1.z * w1v.z + fv1.w * w1v.w;
        }
        // reduce feature-eighths within each role group of 8 lanes
#pragma unroll
        for (int k = 0; k < O; k++) {
            acc[k] += __shfl_down_sync(0xffffffffu, acc[k], 4);
            acc[k] += __shfl_down_sync(0xffffffffu, acc[k], 2);
            acc[k] += __shfl_down_sync(0xffffffffu, acc[k], 1);
        }
        if (q8 == 0) {
            float* dst = sPair + wid * 36 + role * 9;
#pragma unroll
            for (int k = 0; k < O; k++) dst[k] = acc[k];
        }
    }
    __syncthreads();

    // ---------- merges (atomic-free in-block; one RED per stat) ----------
    if (tid < O * 8) {
        int k = tid >> 3, q = tid & 7;
        // q0,1: u=bs-bt (q1 squared); q2,3: v=as-at; q4:bs q5:as q6:bs^2 q7:as^2
        int off1 = (q < 2) ? 9 : (q < 4) ? 0 : ((q == 4 || q == 6) ? 9 : 0);
        bool use_sub = (q < 4);
        bool sq = (q < 4) ? (q & 1) : (q >= 6);
        float s = 0.f;
#pragma unroll
        for (int p = 0; p < PPB; p++) {
            const float* r = sPair + p * 36;
            float x = r[off1 + k];
            if (use_sub) x -= r[off1 + 18 + k];
            s += sq ? x * x : x;
        }
        atomicAdd(&g_acc[tid], s);
    } else if (tid >= 128) {
        int t2 = tid - 128;
        int tc = t2 >> 4, v = t2 & 15;
        float fSA = 0.f, fSB = 0.f;
        int c1 = 0, c2 = 0;
#pragma unroll
        for (int p = 0; p < PPB; p++) {
            int tv1 = sTT[p * 16 + tc];
            int tv2 = sTT[p * 16 + 8 + tc];
            float av = sPair[p * 36 + 1 + tc];
            float bv = sPair[p * 36 + 10 + tc];
            if (tv1 == v) { fSA += av; c1++; }
            if (tv2 == v) { fSB += bv; c2++; }
        }
        atomicAdd(&g_SA[t2], fSA);
        atomicAdd(&g_SB[t2], fSB);
        atomicAdd(&g_c1[t2], c1);
        atomicAdd(&g_c2[t2], c2);
    } else if (tid == 126) {
        atomicAdd(&g_ce, s_ce);
    } else if (tid == 127) {
        atomicAdd(&g_kl, s_kl);
    }

    // ================= last-block epilogue (all fp32) =================
    __threadfence();
    if (tid == 0)
        s_last = (atomicAdd(&g_cnt, 1u) == (unsigned)(NBLOCKS - 1));
    __syncthreads();
    if (!s_last) return;
    __threadfence();

    volatile float* vacc = g_acc;
    volatile float* vSA  = g_SA;
    volatile float* vSB  = g_SB;
    volatile int*   vc1  = g_c1;
    volatile int*   vc2  = g_c2;

    const float n = 1024.f;
    const float N2 = 1048576.f;
    const float INV_N2 = 1.f / 1048576.f;

    // phase A: per-bin pair sums (128 thr) + acc copy (72 thr)
    if (tid < 128) {
        int tc = tid >> 4;
        float c1 = (float)vc1[tid];
        float c2 = (float)vc2[tid];
        float bias = b2[tc + 1];
        m_sh[tid] = c1 * vSB[tid] + c2 * vSA[tid] + c1 * c2 * bias;
        p_sh[tid] = c1 * c2;
    } else if (tid - 128 < O * 8) {
        facc[tid - 128] = vacc[tid - 128];
    }
    __syncthreads();

    // phase B: per-tc bin sums (8 thr) + per-k D2 (9 thr, disjoint range)
    if (tid < 8) {
        float ms = 0.f, ps = 0.f;
#pragma unroll
        for (int v = 0; v < NBIN; v++) { ms += m_sh[tid * NBIN + v]; ps += p_sh[tid * NBIN + v]; }
        matchS[tid] = ms; pairS[tid] = ps;
    } else if (tid >= 32 && tid < 32 + O) {
        int k = tid - 32;
        float Su = facc[k*8+0], Su2 = facc[k*8+1], Sv = facc[k*8+2], Sv2 = facc[k*8+3];
        float ck = b2[k] - b1[k];
        D2s[k] = n * Su2 + n * Sv2 + 2.f * Su * Sv
               + 2.f * ck * n * (Su + Sv) + N2 * ck * ck;
    }
    __syncthreads();

    // phase C: E3 per policy column (7 thr), E1, E2
    if (tid < 7) {
        int k = tid + 2, t = tid + 1;
        float Sb = facc[k*8+4], Sa = facc[k*8+5], Sb2 = facc[k*8+6], Sa2 = facc[k*8+7];
        float ck = b2[k];
        float Sp2 = n * Sb2 + n * Sa2 + 2.f * Sb * Sa
                  + 2.f * ck * n * (Sb + Sa) + N2 * ck * ck;
        float Sp  = n * (Sb + Sa) + N2 * ck;
        float Spg = 2.f * matchS[t] - Sp;
        E3s[tid] = Sp2 - 2.f * Spg + N2;
    } else if (tid == 8) {
        // gId == 1 +/- few float ULP  =>  log(gId) == gId - 1
        float gId = (1.0f / 1023.0f + 1.0f) - 1.0f / 1023.0f;
        float Sb0 = facc[0*8+4], Sa0 = facc[0*8+5];
        E12[0] = (n * gId * (gId - 1.0f) - gId * (Sb0 + Sa0 + n * b2[0])) * INV_N2;
    } else if (tid == 9) {
        float gCp = (1.0f / 99.0f + 1.0f) - 1.0f / 99.0f;
        E12[1] = 0.5f * (pairS[0] * gCp * (gCp - 1.0f) - gCp * matchS[0]) * INV_N2;
    }
    __syncthreads();

    // phase D: scalar combine
    if (tid == 0) {
        float sumDP = 0.f;
#pragma unroll
        for (int k = 2; k < O; k++) sumDP += D2s[k];
        float klp = D2s[0] * INV_N2 + 0.5f * D2s[1] * INV_N2
                  + sumDP * (0.001f * INV_N2 / 7.0f);

        float E3 = 0.f;
#pragma unroll
        for (int m = 0; m < 7; m++) E3 += E3s[m];
        E3 *= 0.001f * INV_N2 / 7.0f;

        float ce = *(volatile float*)&g_ce;
        float kl = *(volatile float*)&g_kl;
        float policy = klp + E12[0] + E12[1] + E3;
        out[0] = ce * (1.0f / (float)BATCH)
               + kl * (16.0f / ((float)BATCH * (float)NCLS))
               + policy;
    }
    __syncthreads();

    // reset scratch for next replay
    if (tid < O * 8) g_acc[tid] = 0.f;
    if (tid < 8 * NBIN) { g_SA[tid] = 0.f; g_SB[tid] = 0.f; g_c1[tid] = 0; g_c2[tid] = 0; }
    if (tid == 0) { g_ce = 0.f; g_kl = 0.f; g_cnt = 0u; }
}

// ---------------- launch ----------------
extern "C" void kernel_launch(void* const* d_in, const int* in_sizes, int n_in,
                              void* d_out, int out_size)
{
    const float* sl = (const float*)d_in[0];   // student_logits (2048,100)
    const float* tl = (const float*)d_in[1];   // teacher_logits (2048,100)
    const float* sp = (const float*)d_in[2];   // student_policy (2048,64)
    const float* tp = (const float*)d_in[3];   // teacher_policy (2048,64)
    const float* W1 = (const float*)d_in[4];   // (9,128)
    const float* b1 = (const float*)d_in[5];   // (9,)
    const float* W2 = (const float*)d_in[6];   // (9,128)
    const float* b2 = (const float*)d_in[7];   // (9,)
    const int*   tg = (const int*)d_in[8];     // (2048,1,8)

    fused_kernel<<<NBLOCKS, 256>>>(sl, tl, sp, tp, W1, b1, W2, b2, tg, (float*)d_out);
}

// round 14
// speedup vs baseline: 1.3612x; 1.1791x over previous
#include <cuda_runtime.h>
#include <math.h>
#include <stdint.h>

#define BATCH    2048
#define NCLS     100
#define FH       64        // FEATURE_NUMS/2
#define O        9         // POLICY_NUMS + 2
#define NBIN     16
#define LBLK     256       // logits blocks: 8 rows each (1 row/warp)
#define PBLK     128       // policy blocks: 8 pairs each (1 pair/warp)
#define NBLOCKS  (LBLK + PBLK)
#define WSZ      (O * 2 * FH)    // 1152 floats per weight matrix
#define PPB      8         // pairs per policy block

// ---------------- scratch (device globals; zero at load, re-zeroed each run) ---
__device__ float g_ce, g_kl;
// per-k stats [k][q], q: 0 Su,1 Su2,2 Sv,3 Sv2,4 Sb,5 Sa,6 Sb2,7 Sa2
__device__ float g_acc[O * 8];
__device__ float g_SA[8 * NBIN], g_SB[8 * NBIN];
__device__ int   g_c1[8 * NBIN], g_c2[8 * NBIN];
__device__ unsigned int g_cnt;

__global__ __launch_bounds__(256) void fused_kernel(
    const float* __restrict__ sl, const float* __restrict__ tl,
    const float* __restrict__ sp, const float* __restrict__ tp,
    const float* __restrict__ W1, const float* __restrict__ b1,
    const float* __restrict__ W2, const float* __restrict__ b2,
    const int*  __restrict__ tg, float* __restrict__ out)
{
    __shared__ float  Ws[2 * WSZ];         // [W2 | W1]  (policy blocks only)
    __shared__ float  sPair[PPB * 36];     // per-pair as[9],bs[9],at[9],bt[9]
    __shared__ int    sTT[PPB * 16];       // targets for this block's 16 rows
    __shared__ float  s_ce, s_kl;
    __shared__ float  m_sh[128], p_sh[128];
    __shared__ float  matchS[8], pairS[8], D2s[O], E3s[7], E12[2], facc[O * 8];
    __shared__ int s_last;

    const int tid  = threadIdx.x;
    const int bid  = blockIdx.x;
    const int wid  = tid >> 5;
    const int lane = tid & 31;

    if (bid < LBLK) {
        // ========= logits block: CE + KL, one row per warp (no max-sub) =========
        if (tid == 0) { s_ce = 0.f; s_kl = 0.f; }
        __syncthreads();

        int row = bid * 8 + wid;
        const float4* s4 = (const float4*)(sl + row * NCLS);
        const float4* t4 = (const float4*)(tl + row * NCLS);

        float sv[4], tv[4];
        bool act = lane < 25;                   // 25 float4 = 100 cols
        float S1 = 0.f, S4 = 0.f, T4 = 0.f, D = 0.f;
        if (act) {
            float4 a = s4[lane], b = t4[lane];
            sv[0]=a.x; sv[1]=a.y; sv[2]=a.z; sv[3]=a.w;
            tv[0]=b.x; tv[1]=b.y; tv[2]=b.z; tv[3]=b.w;
#pragma unroll
            for (int i = 0; i < 4; i++) {
                float s4a = sv[i] * 0.25f;
                float ta  = tv[i] * 0.25f;
                float es  = __expf(s4a);
                float te  = __expf(ta);
                float es2 = es * es;
                S1 += es2 * es2;                // exp(sv) = (exp(sv/4))^4
                S4 += es;
                T4 += te;
                D  += te * (ta - s4a);          // U - V folded
            }
        }
#pragma unroll
        for (int o = 16; o; o >>= 1) {
            S1 += __shfl_down_sync(0xffffffffu, S1, o);
            S4 += __shfl_down_sync(0xffffffffu, S4, o);
            T4 += __shfl_down_sync(0xffffffffu, T4, o);
            D  += __shfl_down_sync(0xffffffffu, D,  o);
        }

        // CE label (in [0,10) -> data lives in lanes 0..2 of the float4 layout)
        int label = tg[row * 8];
        int elem = label & 3;
        float cand = (elem == 0) ? sv[0] : (elem == 1) ? sv[1] : (elem == 2) ? sv[2] : sv[3];
        float slab = __shfl_sync(0xffffffffu, cand, label >> 2);

        if (lane == 0) {
            float kl = D / T4 + __logf(S4) - __logf(T4);
            float ce = __logf(S1) - slab;
            atomicAdd(&s_ce, ce);
            atomicAdd(&s_kl, kl);
        }
        __syncthreads();
        if (tid == 0) atomicAdd(&g_ce, s_ce);
        else if (tid == 32) atomicAdd(&g_kl, s_kl);
    } else {
        // ========= policy block: 8 pairs, warp per pair, atomic-free merges ======
        int pb = bid - LBLK;                   // 0..127
        {
            const float4* w2v = (const float4*)W2;   // 288 float4
            const float4* w1v = (const float4*)W1;
            float4* wsv = (float4*)Ws;
#pragma unroll
            for (int i = tid; i < 576; i += 256)
                wsv[i] = (i < 288) ? w2v[i] : w1v[i - 288];
            if (tid < 32)
                ((int4*)sTT)[tid] = ((const int4*)(tg + pb * 128))[tid];
        }

        // lane -> role (4) x feature-eighth (8)
        const int j    = pb * PPB + wid;       // global pair 0..1023
        const int role = lane >> 3;            // 0:as 1:bs 2:at 3:bt
        const int q8   = lane & 7;
        const int c0   = q8 * 8;
        const float* fbase = ((role < 2) ? sp : tp) + (2 * j + (role & 1)) * FH + c0;
        float4 fv0 = ((const float4*)fbase)[0];
        float4 fv1 = ((const float4*)fbase)[1];
        __syncthreads();   // Ws + sTT ready

        const float* wbase = Ws + ((role >= 2) ? WSZ : 0) + (role & 1) * FH + c0;
        float acc[O];
#pragma unroll
        for (int k = 0; k < O; k++) {
            const float4* w = (const float4*)(wbase + k * 2 * FH);
            float4 w0 = w[0], w1v = w[1];
            acc[k] = fv0.x * w0.x + fv0.y * w0.y + fv0.z * w0.z + fv0.w * w0.w
                   + fv1.x * w1v.x + fv1.y * w1v.y + fv1.z * w1v.z + fv1.w * w1v.w;
        }
        // reduce feature-eighths within each role group of 8 lanes
#pragma unroll
        for (int k = 0; k < O; k++) {
            acc[k] += __shfl_down_sync(0xffffffffu, acc[k], 4);
            acc[k] += __shfl_down_sync(0xffffffffu, acc[k], 2);
            acc[k] += __shfl_down_sync(0xffffffffu, acc[k], 1);
        }
        if (q8 == 0) {
            float* dst = sPair + wid * 36 + role * 9;
#pragma unroll
            for (int k = 0; k < O; k++) dst[k] = acc[k];
        }
        __syncthreads();

        // merges (atomic-free in-block; one RED per stat)
        if (tid < O * 8) {
            int k = tid >> 3, q = tid & 7;
            // q0,1: u=bs-bt (q1 sq); q2,3: v=as-at; q4:bs q5:as q6:bs^2 q7:as^2
            int off1 = (q < 2) ? 9 : (q < 4) ? 0 : ((q == 4 || q == 6) ? 9 : 0);
            bool use_sub = (q < 4);
            bool sq = (q < 4) ? (q & 1) : (q >= 6);
            float s = 0.f;
#pragma unroll
            for (int p = 0; p < PPB; p++) {
                const float* r = sPair + p * 36;
                float x = r[off1 + k];
                if (use_sub) x -= r[off1 + 18 + k];
                s += sq ? x * x : x;
            }
            atomicAdd(&g_acc[tid], s);
        } else if (tid >= 128) {
            int t2 = tid - 128;
            int tc = t2 >> 4, v = t2 & 15;
            float fSA = 0.f, fSB = 0.f;
            int c1 = 0, c2 = 0;
#pragma unroll
            for (int p = 0; p < PPB; p++) {
                int tv1 = sTT[p * 16 + tc];
                int tv2 = sTT[p * 16 + 8 + tc];
                float av = sPair[p * 36 + 1 + tc];
                float bv = sPair[p * 36 + 10 + tc];
                if (tv1 == v) { fSA += av; c1++; }
                if (tv2 == v) { fSB += bv; c2++; }
            }
            atomicAdd(&g_SA[t2], fSA);
            atomicAdd(&g_SB[t2], fSB);
            atomicAdd(&g_c1[t2], c1);
            atomicAdd(&g_c2[t2], c2);
        }
    }

    // ================= last-block epilogue (all fp32) =================
    __threadfence();
    if (tid == 0)
        s_last = (atomicAdd(&g_cnt, 1u) == (unsigned)(NBLOCKS - 1));
    __syncthreads();
    if (!s_last) return;
    __threadfence();

    volatile float* vacc = g_acc;
    volatile float* vSA  = g_SA;
    volatile float* vSB  = g_SB;
    volatile int*   vc1  = g_c1;
    volatile int*   vc2  = g_c2;

    const float n = 1024.f;
    const float N2 = 1048576.f;
    const float INV_N2 = 1.f / 1048576.f;

    // phase A: per-bin pair sums (128 thr) + acc copy (72 thr)
    if (tid < 128) {
        int tc = tid >> 4;
        float c1 = (float)vc1[tid];
        float c2 = (float)vc2[tid];
        float bias = b2[tc + 1];
        m_sh[tid] = c1 * vSB[tid] + c2 * vSA[tid] + c1 * c2 * bias;
        p_sh[tid] = c1 * c2;
    } else if (tid - 128 < O * 8) {
        facc[tid - 128] = vacc[tid - 128];
    }
    __syncthreads();

    // phase B: per-tc bin sums (8 thr) + per-k D2 (9 thr, disjoint range)
    if (tid < 8) {
        float ms = 0.f, ps = 0.f;
#pragma unroll
        for (int v = 0; v < NBIN; v++) { ms += m_sh[tid * NBIN + v]; ps += p_sh[tid * NBIN + v]; }
        matchS[tid] = ms; pairS[tid] = ps;
    } else if (tid >= 32 && tid < 32 + O) {
        int k = tid - 32;
        float Su = facc[k*8+0], Su2 = facc[k*8+1], Sv = facc[k*8+2], Sv2 = facc[k*8+3];
        float ck = b2[k] - b1[k];
        D2s[k] = n * Su2 + n * Sv2 + 2.f * Su * Sv
               + 2.f * ck * n * (Su + Sv) + N2 * ck * ck;
    }
    __syncthreads();

    // phase C: E3 per policy column (7 thr), E1, E2
    if (tid < 7) {
        int k = tid + 2, t = tid + 1;
        float Sb = facc[k*8+4], Sa = facc[k*8+5], Sb2 = facc[k*8+6], Sa2 = facc[k*8+7];
        float ck = b2[k];
        float Sp2 = n * Sb2 + n * Sa2 + 2.f * Sb * Sa
                  + 2.f * ck * n * (Sb + Sa) + N2 * ck * ck;
        float Sp  = n * (Sb + Sa) + N2 * ck;
        float Spg = 2.f * matchS[t] - Sp;
        E3s[tid] = Sp2 - 2.f * Spg + N2;
    } else if (tid == 8) {
        // gId == 1 +/- few float ULP  =>  log(gId) == gId - 1
        float gId = (1.0f / 1023.0f + 1.0f) - 1.0f / 1023.0f;
        float Sb0 = facc[0*8+4], Sa0 = facc[0*8+5];
        E12[0] = (n * gId * (gId - 1.0f) - gId * (Sb0 + Sa0 + n * b2[0])) * INV_N2;
    } else if (tid == 9) {
        float gCp = (1.0f / 99.0f + 1.0f) - 1.0f / 99.0f;
        E12[1] = 0.5f * (pairS[0] * gCp * (gCp - 1.0f) - gCp * matchS[0]) * INV_N2;
    }
    __syncthreads();

    // phase D: scalar combine
    if (tid == 0) {
        float sumDP = 0.f;
#pragma unroll
        for (int k = 2; k < O; k++) sumDP += D2s[k];
        float klp = D2s[0] * INV_N2 + 0.5f * D2s[1] * INV_N2
                  + sumDP * (0.001f * INV_N2 / 7.0f);

        float E3 = 0.f;
#pragma unroll
        for (int m = 0; m < 7; m++) E3 += E3s[m];
        E3 *= 0.001f * INV_N2 / 7.0f;

        float ce = *(volatile float*)&g_ce;
        float kl = *(volatile float*)&g_kl;
        float policy = klp + E12[0] + E12[1] + E3;
        out[0] = ce * (1.0f / (float)BATCH)
               + kl * (16.0f / ((float)BATCH * (float)NCLS))
               + policy;
    }
    __syncthreads();

    // reset scratch for next replay
    if (tid < O * 8) g_acc[tid] = 0.f;
    if (tid < 8 * NBIN) { g_SA[tid] = 0.f; g_SB[tid] = 0.f; g_c1[tid] = 0; g_c2[tid] = 0; }
    if (tid == 0) { g_ce = 0.f; g_kl = 0.f; g_cnt = 0u; }
}

// ---------------- launch ----------------
extern "C" void kernel_launch(void* const* d_in, const int* in_sizes, int n_in,
                              void* d_out, int out_size)
{
    const float* sl = (const float*)d_in[0];   // student_logits (2048,100)
    const float* tl = (const float*)d_in[1];   // teacher_logits (2048,100)
    const float* sp = (const float*)d_in[2];   // student_policy (2048,64)
    const float* tp = (const float*)d_in[3];   // teacher_policy (2048,64)
    const float* W1 = (const float*)d_in[4];   // (9,128)
    const float* b1 = (const float*)d_in[5];   // (9,)
    const float* W2 = (const float*)d_in[6];   // (9,128)
    const float* b2 = (const float*)d_in[7];   // (9,)
    const int*   tg = (const int*)d_in[8];     // (2048,1,8)

    fused_kernel<<<NBLOCKS, 256>>>(sl, tl, sp, tp, W1, b1, W2, b2, tg, (float*)d_out);
}